// round 12
// baseline (speedup 1.0000x reference)
#include <cuda_runtime.h>
#include <cuda_bf16.h>
#include <cstdint>

#define B 8
#define C 256
#define H 64
#define W 64
#define MAXOFF 16.0f
#define NCH 36                       // K chunks of 64 over K=2304

__device__ float  g_om[B * 27 * H * W];
__device__ uint32_t g_dpk[B * H * 9 * W];    // packed: y0row | y1row<<12 | dx<<24
__device__ float4 g_dw[B * H * 9 * W];
__device__ uint4  g_wpack[2 * NCH * 2048];   // [half][chunk][oc][kq] bf16 weights

// ---- PTX helpers ----------------------------------------------------------
__device__ __forceinline__ uint32_t smem_u32(const void* p) {
    uint32_t a;
    asm("{ .reg .u64 t; cvta.to.shared.u64 t, %1; cvt.u32.u64 %0, t; }" : "=r"(a) : "l"(p));
    return a;
}
#define LDM4(r, addr) \
    asm volatile("ldmatrix.sync.aligned.m8n8.x4.shared.b16 {%0,%1,%2,%3}, [%4];" \
        : "=r"((r)[0]), "=r"((r)[1]), "=r"((r)[2]), "=r"((r)[3]) : "r"(addr))
#define MMA(acc, a, b0, b1) \
    asm volatile("mma.sync.aligned.m16n8k16.row.col.f32.bf16.bf16.f32 " \
        "{%0,%1,%2,%3}, {%4,%5,%6,%7}, {%8,%9}, {%0,%1,%2,%3};" \
        : "+f"((acc)[0]), "+f"((acc)[1]), "+f"((acc)[2]), "+f"((acc)[3]) \
        : "r"((a)[0]), "r"((a)[1]), "r"((a)[2]), "r"((a)[3]), "r"(b0), "r"(b1))
#define CPA16(dst, src) \
    asm volatile("{ .reg .u64 g; cvta.to.global.u64 g, %1; cp.async.cg.shared.global [%0], [g], 16; }" \
        :: "r"(dst), "l"(src) : "memory")
#define CPA_COMMIT() asm volatile("cp.async.commit_group;" ::: "memory")
#define CPA_WAIT0()  asm volatile("cp.async.wait_group 0;" ::: "memory")

// ---- prep: pack reg_w -> bf16 hi/lo, layout [half][chunk][oc][k] ----------
__global__ void k_prep(const float* __restrict__ reg_w) {
    int t = blockIdx.x * blockDim.x + threadIdx.x;
    if (t >= 2 * NCH * 2048) return;
    int u = t & 2047, chunk = (t >> 11) % NCH, half = t / (NCH * 2048);
    int oc = u >> 3, col = (u & 7) * 8;
    unsigned short s[8];
#pragma unroll
    for (int e = 0; e < 8; e++) {
        float wv = reg_w[oc * 2304 + chunk * 64 + col + e];
        __nv_bfloat16 hi = __float2bfloat16(wv);
        __nv_bfloat16 o = half ? __float2bfloat16(wv - __bfloat162float(hi)) : hi;
        s[e] = *reinterpret_cast<unsigned short*>(&o);
    }
    uint4 v;
    v.x = s[0] | ((unsigned)s[1] << 16); v.y = s[2] | ((unsigned)s[3] << 16);
    v.z = s[4] | ((unsigned)s[5] << 16); v.w = s[6] | ((unsigned)s[7] << 16);
    g_wpack[t] = v;
}

// ---- 27-ch 3x3 conv (unchanged) ------------------------------------------
__global__ void __launch_bounds__(256) k_conv_om(
    const float* __restrict__ x, const float* __restrict__ ow, const float* __restrict__ ob,
    const float* __restrict__ mw, const float* __restrict__ mb)
{
    __shared__ float xs[16 * 3 * 72];
    __shared__ float w1[144 * 28];
    const int bh = blockIdx.x, b = bh >> 6, h = bh & 63;
    const int tid = threadIdx.x, tx = tid & 15, ty = tid >> 4;
    float acc0[4] = {0,0,0,0}, acc1[4] = {0,0,0,0};

    for (int c0 = 0; c0 < C; c0 += 16) {
        for (int u = tid; u < 16 * 3 * 66; u += 256) {
            int cc = u / 198, r2 = u % 198, ry = r2 / 66, col = r2 % 66;
            int y = h - 1 + ry, xw = col - 1;
            float v = 0.f;
            if (y >= 0 && y < H && xw >= 0 && xw < W) v = x[((b * C + c0 + cc) * H + y) * W + xw];
            xs[(cc * 3 + ry) * 72 + col] = v;
        }
        for (int u = tid; u < 144 * 27; u += 256) {
            int rr = u / 27, o = u % 27, cc = rr / 9, kk = rr % 9;
            w1[rr * 28 + o] = (o < 18) ? ow[(o * C + c0 + cc) * 9 + kk] : mw[((o - 18) * C + c0 + cc) * 9 + kk];
        }
        __syncthreads();
#pragma unroll 4
        for (int cc = 0; cc < 16; cc++)
#pragma unroll
            for (int ky = 0; ky < 3; ky++) {
                const float* row = &xs[(cc * 3 + ky) * 72 + tx * 4];
                float4 a4 = *(const float4*)row;
                float2 b2 = *(const float2*)(row + 4);
                float xr[6] = {a4.x, a4.y, a4.z, a4.w, b2.x, b2.y};
#pragma unroll
                for (int kx = 0; kx < 3; kx++) {
                    int r = cc * 9 + ky * 3 + kx;
                    float wa = w1[r * 28 + ty];
                    float wb = (ty < 11) ? w1[r * 28 + ty + 16] : 0.f;
#pragma unroll
                    for (int ii = 0; ii < 4; ii++) {
                        acc0[ii] = fmaf(wa, xr[ii + kx], acc0[ii]);
                        acc1[ii] = fmaf(wb, xr[ii + kx], acc1[ii]);
                    }
                }
            }
        __syncthreads();
    }
    {
        int o = ty; float bia = (o < 18) ? ob[o] : mb[o - 18];
#pragma unroll
        for (int ii = 0; ii < 4; ii++) {
            float v = acc0[ii] + bia;
            v = (o < 18) ? fminf(fmaxf(v, -MAXOFF), MAXOFF) : 1.f / (1.f + expf(-v));
            g_om[(b * 27 + o) * (H * W) + h * W + tx * 4 + ii] = v;
        }
    }
    if (ty < 11) {
        int o = ty + 16; float bia = (o < 18) ? ob[o] : mb[o - 18];
#pragma unroll
        for (int ii = 0; ii < 4; ii++) {
            float v = acc1[ii] + bia;
            v = (o < 18) ? fminf(fmaxf(v, -MAXOFF), MAXOFF) : 1.f / (1.f + expf(-v));
            g_om[(b * 27 + o) * (H * W) + h * W + tx * 4 + ii] = v;
        }
    }
}

// ---- bilinear descriptors (packed) ----------------------------------------
__global__ void k_build_desc() {
    int t = blockIdx.x * blockDim.x + threadIdx.x;
    if (t >= B * H * 9 * W) return;
    int w = t & 63, k = (t >> 6) % 9, bh = t / 576, h = bh & 63, b = bh >> 6;
    const int hw = h * W + w;
    float dy = g_om[(b * 27 + 2 * k) * (H * W) + hw];
    float dx = g_om[(b * 27 + 2 * k + 1) * (H * W) + hw];
    float m  = g_om[(b * 27 + 18 + k) * (H * W) + hw];
    float py = (float)(h - 1 + k / 3) + dy, px = (float)(w - 1 + k % 3) + dx;
    float y0f = floorf(py), x0f = floorf(px);
    float ly = py - y0f, lx = px - x0f;
    int y0 = (int)y0f, x0 = (int)x0f, y1 = y0 + 1, x1 = x0 + 1;
    float v00 = (y0 >= 0 && y0 < H && x0 >= 0 && x0 < W) ? 1.f : 0.f;
    float v01 = (y0 >= 0 && y0 < H && x1 >= 0 && x1 < W) ? 1.f : 0.f;
    float v10 = (y1 >= 0 && y1 < H && x0 >= 0 && x0 < W) ? 1.f : 0.f;
    float v11 = (y1 >= 0 && y1 < H && x1 >= 0 && x1 < W) ? 1.f : 0.f;
    int cy0 = min(max(y0, 0), H - 1), cy1 = min(max(y1, 0), H - 1);
    int cx0 = min(max(x0, 0), W - 1), cx1 = min(max(x1, 0), W - 1);
    uint32_t i0 = (uint32_t)(cy0 * W + cx0);
    uint32_t i1 = (uint32_t)(cy1 * W + cx0);
    uint32_t dd = (uint32_t)(cx1 - cx0);
    g_dpk[t] = i0 | (i1 << 12) | (dd << 24);
    g_dw[t] = make_float4((1.f - ly) * (1.f - lx) * m * v00, (1.f - ly) * lx * m * v01,
                          ly * (1.f - lx) * m * v10, ly * lx * m * v11);
}

// ---- main: mma.sync bf16 3-pass GEMM with smem-staged x windows ----------
// smem: A hi 16K + lo 16K @0 | B 2 x (hi 32K + lo 32K) @32768
//       X 8ch x 12rows x 256B @163840 (24576) | s_pk @188416 (4608) | s_wt @193024 (18432)
#define SMEM_MM 211456
#define XOFF 163840
#define PKOFF 188416
#define WTOFF 193024
__global__ void __launch_bounds__(256, 1) k_dconv_mma(const float* __restrict__ x, float* __restrict__ out) {
    extern __shared__ char sm[];
    uint32_t* s_pk = (uint32_t*)(sm + PKOFF);
    float4*   s_wt = (float4*)(sm + WTOFF);
    float*    Xf   = (float*)(sm + XOFF);

    const int tid = threadIdx.x, wid = tid >> 5, lid = tid & 31;
    const int b = blockIdx.x >> 5, h0 = (blockIdx.x & 31) * 2;
    const int m0 = (wid & 3) * 32;       // warp M origin (px)
    const int n0 = (wid >> 2) * 128;     // warp N origin (oc)
    const int r0 = min(max(h0 - 5, 0), 52);     // 12-row x window

    // stage descriptors: 1152 = 2 rows x 9 taps x 64 px
    for (int u = tid; u < 1152; u += 256) {
        int g = (b * 64 + h0 + (u >= 576)) * 576 + (u >= 576 ? u - 576 : u);
        s_pk[u] = g_dpk[g];
        s_wt[u] = g_dw[g];
    }

    const uint32_t smb = smem_u32(sm);
    const uint32_t Xsm = smb + XOFF;
    const int ra = m0 + (lid & 15);
    const uint32_t aBase = smb + (uint32_t)ra * 128;
    const uint32_t xa = (uint32_t)(ra & 7) << 4;
    const uint32_t ca = (uint32_t)(lid >> 4) * 16;
    const int rbn = n0 + (lid & 7) + ((lid >> 4) << 3);
    const uint32_t bBase = smb + 32768 + (uint32_t)rbn * 128;
    const uint32_t xb = (uint32_t)(rbn & 7) << 4;
    const uint32_t cb = (uint32_t)((lid >> 3) & 1) * 16;

    float acc[2][16][4];
#pragma unroll
    for (int i = 0; i < 2; i++)
#pragma unroll
        for (int j = 0; j < 16; j++) {
            acc[i][j][0] = 0.f; acc[i][j][1] = 0.f; acc[i][j][2] = 0.f; acc[i][j][3] = 0.f;
        }

    const int px = tid & 127, hb = tid >> 7;
    const int w = px & 63, h2 = px >> 6;
    const float* xb0 = x + (size_t)b * C * 4096;

    // issue async copies for chunk's x window + B tiles
    auto stage = [&](int chunk, int bu) {
        int cA = (chunk * 64) / 9;
        const float* xsrc = xb0 + (size_t)cA * 4096 + r0 * 64;
#pragma unroll
        for (int j = 0; j < 6; j++) {
            int g = tid + j * 256;                  // < 1536
            int ch = g / 192, rem = g - ch * 192;   // 192 16B-granules per channel
            CPA16(Xsm + ch * 3072 + rem * 16, xsrc + ch * 4096 + rem * 4);
        }
        uint32_t Bb = smb + 32768 + (uint32_t)bu * 65536;
        const uint4* bh4 = g_wpack + chunk * 2048;
        const uint4* bl4 = g_wpack + (NCH + chunk) * 2048;
#pragma unroll
        for (int j = 0; j < 8; j++) {
            int u = tid + j * 256;
            uint32_t o = (uint32_t)((u >> 3) * 128 + (u & 7) * 16);
            o ^= ((uint32_t)(u >> 3) & 7) << 4;
            CPA16(Bb + o, bh4 + u);
            CPA16(Bb + 32768 + o, bl4 + u);
        }
        CPA_COMMIT();
    };

    stage(0, 0);

    for (int chunk = 0; chunk < NCH; chunk++) {
        const int bu = chunk & 1;
        CPA_WAIT0();
        __syncthreads();          // x(chunk), B(chunk) landed; A/X buffers free

        // build A from smem x window (global fallback for out-of-window samples)
        {
            char* Ah = sm; char* Al = sm + 16384;
            const uint32_t xpx = ((uint32_t)(px & 7)) << 4;
            int cA = (chunk * 64) / 9;
            int bm = chunk % 9;
#pragma unroll
            for (int kk = 0; kk < 9; kk++) {
                int a = kk - bm; if (a < 0) a += 9;
                int rr = ((a ^ hb) & 1) ? a + 9 : a;
                int d = h2 * 576 + kk * 64 + w;
                uint32_t pk = s_pk[d];
                float4 dw = s_wt[d];
                int i0 = pk & 0xFFF, i1 = (pk >> 12) & 0xFFF, dd = pk >> 24;
                int y0 = i0 >> 6, y1 = i1 >> 6;
                bool inw = (y0 >= r0) && (y1 <= r0 + 11);
                int o0 = (y0 - r0) * 64 + (i0 & 63);
                int o1 = (y1 - r0) * 64 + (i0 & 63);
                int cl = (chunk * 64 + rr) / 9 - cA;
                for (; rr < 64; rr += 18, cl += 2) {
                    float v;
                    if (inw) {
                        const float* xs = Xf + cl * 768;
                        v = dw.x * xs[o0] + dw.y * xs[o0 + dd]
                          + dw.z * xs[o1] + dw.w * xs[o1 + dd];
                    } else {
                        const float* xp = xb0 + (size_t)(cA + cl) * 4096;
                        v = dw.x * __ldg(xp + i0) + dw.y * __ldg(xp + i0 + dd)
                          + dw.z * __ldg(xp + i1) + dw.w * __ldg(xp + i1 + dd);
                    }
                    __nv_bfloat16 hi = __float2bfloat16(v);
                    __nv_bfloat16 lo = __float2bfloat16(v - __bfloat162float(hi));
                    uint32_t o = ((uint32_t)(px * 128 + rr * 2)) ^ xpx;
                    *(__nv_bfloat16*)(Ah + o) = hi;
                    *(__nv_bfloat16*)(Al + o) = lo;
                }
            }
        }
        __syncthreads();          // A ready; X consumed

        if (chunk + 1 < NCH) stage(chunk + 1, bu ^ 1);   // overlaps MMA below

        const uint32_t Boff = (uint32_t)bu * 65536;
#pragma unroll
        for (int ks = 0; ks < 4; ks++) {
            uint32_t aH[2][4], aL[2][4];
#pragma unroll
            for (int mm = 0; mm < 2; mm++) {
                uint32_t ad = aBase + (uint32_t)mm * 2048 + (((uint32_t)ks * 32 + ca) ^ xa);
                LDM4(aH[mm], ad);
                LDM4(aL[mm], ad + 16384);
            }
#pragma unroll
            for (int nn2 = 0; nn2 < 8; nn2++) {
                uint32_t bh[4], bl[4];
                uint32_t bd = bBase + Boff + (uint32_t)nn2 * 2048 + (((uint32_t)ks * 32 + cb) ^ xb);
                LDM4(bh, bd);
                LDM4(bl, bd + 32768);
#pragma unroll
                for (int mm = 0; mm < 2; mm++) {
                    MMA(acc[mm][2 * nn2],     aH[mm], bh[0], bh[1]);
                    MMA(acc[mm][2 * nn2 + 1], aH[mm], bh[2], bh[3]);
                    MMA(acc[mm][2 * nn2],     aL[mm], bh[0], bh[1]);
                    MMA(acc[mm][2 * nn2 + 1], aL[mm], bh[2], bh[3]);
                    MMA(acc[mm][2 * nn2],     aH[mm], bl[0], bl[1]);
                    MMA(acc[mm][2 * nn2 + 1], aH[mm], bl[2], bl[3]);
                }
            }
        }
    }

    // epilogue (verified mapping)
    {
        const int g = lid >> 2, tc = lid & 3;
#pragma unroll
        for (int mm = 0; mm < 2; mm++) {
            int px0 = m0 + mm * 16 + g, px1 = px0 + 8;
            size_t i0 = (size_t)(h0 + (px0 >> 6)) * 64 + (px0 & 63);
            size_t i1 = (size_t)(h0 + (px1 >> 6)) * 64 + (px1 & 63);
#pragma unroll
            for (int nn = 0; nn < 16; nn++) {
                int oc = n0 + nn * 8 + 2 * tc;
                size_t r0o = (size_t)(b * 256 + oc) * 4096;
                out[r0o + i0]        = acc[mm][nn][0];
                out[r0o + 4096 + i0] = acc[mm][nn][1];
                out[r0o + i1]        = acc[mm][nn][2];
                out[r0o + 4096 + i1] = acc[mm][nn][3];
            }
        }
    }
}

// ---------------------------------------------------------------------------
extern "C" void kernel_launch(void* const* d_in, const int* in_sizes, int n_in,
                              void* d_out, int out_size) {
    const float* x  = (const float*)d_in[0];
    const float* ow = (const float*)d_in[1];
    const float* ob = (const float*)d_in[2];
    const float* mw = (const float*)d_in[3];
    const float* mb = (const float*)d_in[4];
    const float* rw = (const float*)d_in[5];
    float* out = (float*)d_out;
    (void)in_sizes; (void)n_in; (void)out_size;

    cudaFuncSetAttribute(k_dconv_mma, cudaFuncAttributeMaxDynamicSharedMemorySize, SMEM_MM);
    k_prep<<<(2 * NCH * 2048 + 255) / 256, 256>>>(rw);
    k_conv_om<<<B * H, 256>>>(x, ow, ob, mw, mb);
    k_build_desc<<<(B * H * 9 * W + 255) / 256, 256>>>();
    k_dconv_mma<<<B * (H / 2), 256, SMEM_MM>>>(x, out);
}

// round 13
// speedup vs baseline: 1.5538x; 1.5538x over previous
#include <cuda_runtime.h>
#include <cuda_bf16.h>
#include <cstdint>

#define B 8
#define C 256
#define H 64
#define W 64
#define MAXOFF 16.0f
#define NCH 36                       // K chunks of 64 over K=2304

__device__ float  g_om[B * 27 * H * W];
__device__ uint32_t g_dpk[B * H * 9 * W];    // packed: y0row | y1row<<12 | dx<<24
__device__ float4 g_dw[B * H * 9 * W];
__device__ uint4  g_wpack[2 * NCH * 2048];   // [half][chunk][oc][kq] bf16 weights

// ---- PTX helpers ----------------------------------------------------------
__device__ __forceinline__ uint32_t smem_u32(const void* p) {
    uint32_t a;
    asm("{ .reg .u64 t; cvta.to.shared.u64 t, %1; cvt.u32.u64 %0, t; }" : "=r"(a) : "l"(p));
    return a;
}
#define LDM4(r, addr) \
    asm volatile("ldmatrix.sync.aligned.m8n8.x4.shared.b16 {%0,%1,%2,%3}, [%4];" \
        : "=r"((r)[0]), "=r"((r)[1]), "=r"((r)[2]), "=r"((r)[3]) : "r"(addr))
#define MMA(acc, a, b0, b1) \
    asm volatile("mma.sync.aligned.m16n8k16.row.col.f32.bf16.bf16.f32 " \
        "{%0,%1,%2,%3}, {%4,%5,%6,%7}, {%8,%9}, {%0,%1,%2,%3};" \
        : "+f"((acc)[0]), "+f"((acc)[1]), "+f"((acc)[2]), "+f"((acc)[3]) \
        : "r"((a)[0]), "r"((a)[1]), "r"((a)[2]), "r"((a)[3]), "r"(b0), "r"(b1))

// ---- prep: pack reg_w -> bf16 hi/lo, layout [half][chunk][oc][k] ----------
__global__ void k_prep(const float* __restrict__ reg_w) {
    int t = blockIdx.x * blockDim.x + threadIdx.x;
    if (t >= 2 * NCH * 2048) return;
    int u = t & 2047, chunk = (t >> 11) % NCH, half = t / (NCH * 2048);
    int oc = u >> 3, col = (u & 7) * 8;
    unsigned short s[8];
#pragma unroll
    for (int e = 0; e < 8; e++) {
        float wv = reg_w[oc * 2304 + chunk * 64 + col + e];
        __nv_bfloat16 hi = __float2bfloat16(wv);
        __nv_bfloat16 o = half ? __float2bfloat16(wv - __bfloat162float(hi)) : hi;
        s[e] = *reinterpret_cast<unsigned short*>(&o);
    }
    uint4 v;
    v.x = s[0] | ((unsigned)s[1] << 16); v.y = s[2] | ((unsigned)s[3] << 16);
    v.z = s[4] | ((unsigned)s[5] << 16); v.w = s[6] | ((unsigned)s[7] << 16);
    g_wpack[t] = v;
}

// ---- 27-ch 3x3 conv (unchanged) ------------------------------------------
__global__ void __launch_bounds__(256) k_conv_om(
    const float* __restrict__ x, const float* __restrict__ ow, const float* __restrict__ ob,
    const float* __restrict__ mw, const float* __restrict__ mb)
{
    __shared__ float xs[16 * 3 * 72];
    __shared__ float w1[144 * 28];
    const int bh = blockIdx.x, b = bh >> 6, h = bh & 63;
    const int tid = threadIdx.x, tx = tid & 15, ty = tid >> 4;
    float acc0[4] = {0,0,0,0}, acc1[4] = {0,0,0,0};

    for (int c0 = 0; c0 < C; c0 += 16) {
        for (int u = tid; u < 16 * 3 * 66; u += 256) {
            int cc = u / 198, r2 = u % 198, ry = r2 / 66, col = r2 % 66;
            int y = h - 1 + ry, xw = col - 1;
            float v = 0.f;
            if (y >= 0 && y < H && xw >= 0 && xw < W) v = x[((b * C + c0 + cc) * H + y) * W + xw];
            xs[(cc * 3 + ry) * 72 + col] = v;
        }
        for (int u = tid; u < 144 * 27; u += 256) {
            int rr = u / 27, o = u % 27, cc = rr / 9, kk = rr % 9;
            w1[rr * 28 + o] = (o < 18) ? ow[(o * C + c0 + cc) * 9 + kk] : mw[((o - 18) * C + c0 + cc) * 9 + kk];
        }
        __syncthreads();
#pragma unroll 4
        for (int cc = 0; cc < 16; cc++)
#pragma unroll
            for (int ky = 0; ky < 3; ky++) {
                const float* row = &xs[(cc * 3 + ky) * 72 + tx * 4];
                float4 a4 = *(const float4*)row;
                float2 b2 = *(const float2*)(row + 4);
                float xr[6] = {a4.x, a4.y, a4.z, a4.w, b2.x, b2.y};
#pragma unroll
                for (int kx = 0; kx < 3; kx++) {
                    int r = cc * 9 + ky * 3 + kx;
                    float wa = w1[r * 28 + ty];
                    float wb = (ty < 11) ? w1[r * 28 + ty + 16] : 0.f;
#pragma unroll
                    for (int ii = 0; ii < 4; ii++) {
                        acc0[ii] = fmaf(wa, xr[ii + kx], acc0[ii]);
                        acc1[ii] = fmaf(wb, xr[ii + kx], acc1[ii]);
                    }
                }
            }
        __syncthreads();
    }
    {
        int o = ty; float bia = (o < 18) ? ob[o] : mb[o - 18];
#pragma unroll
        for (int ii = 0; ii < 4; ii++) {
            float v = acc0[ii] + bia;
            v = (o < 18) ? fminf(fmaxf(v, -MAXOFF), MAXOFF) : 1.f / (1.f + expf(-v));
            g_om[(b * 27 + o) * (H * W) + h * W + tx * 4 + ii] = v;
        }
    }
    if (ty < 11) {
        int o = ty + 16; float bia = (o < 18) ? ob[o] : mb[o - 18];
#pragma unroll
        for (int ii = 0; ii < 4; ii++) {
            float v = acc1[ii] + bia;
            v = (o < 18) ? fminf(fmaxf(v, -MAXOFF), MAXOFF) : 1.f / (1.f + expf(-v));
            g_om[(b * 27 + o) * (H * W) + h * W + tx * 4 + ii] = v;
        }
    }
}

// ---- bilinear descriptors (packed) ----------------------------------------
__global__ void k_build_desc() {
    int t = blockIdx.x * blockDim.x + threadIdx.x;
    if (t >= B * H * 9 * W) return;
    int w = t & 63, k = (t >> 6) % 9, bh = t / 576, h = bh & 63, b = bh >> 6;
    const int hw = h * W + w;
    float dy = g_om[(b * 27 + 2 * k) * (H * W) + hw];
    float dx = g_om[(b * 27 + 2 * k + 1) * (H * W) + hw];
    float m  = g_om[(b * 27 + 18 + k) * (H * W) + hw];
    float py = (float)(h - 1 + k / 3) + dy, px = (float)(w - 1 + k % 3) + dx;
    float y0f = floorf(py), x0f = floorf(px);
    float ly = py - y0f, lx = px - x0f;
    int y0 = (int)y0f, x0 = (int)x0f, y1 = y0 + 1, x1 = x0 + 1;
    float v00 = (y0 >= 0 && y0 < H && x0 >= 0 && x0 < W) ? 1.f : 0.f;
    float v01 = (y0 >= 0 && y0 < H && x1 >= 0 && x1 < W) ? 1.f : 0.f;
    float v10 = (y1 >= 0 && y1 < H && x0 >= 0 && x0 < W) ? 1.f : 0.f;
    float v11 = (y1 >= 0 && y1 < H && x1 >= 0 && x1 < W) ? 1.f : 0.f;
    int cy0 = min(max(y0, 0), H - 1), cy1 = min(max(y1, 0), H - 1);
    int cx0 = min(max(x0, 0), W - 1), cx1 = min(max(x1, 0), W - 1);
    uint32_t i0 = (uint32_t)(cy0 * W + cx0);
    uint32_t i1 = (uint32_t)(cy1 * W + cx0);
    uint32_t dd = (uint32_t)(cx1 - cx0);
    g_dpk[t] = i0 | (i1 << 12) | (dd << 24);
    g_dw[t] = make_float4((1.f - ly) * (1.f - lx) * m * v00, (1.f - ly) * lx * m * v01,
                          ly * (1.f - lx) * m * v10, ly * lx * m * v11);
}

// ---- main: mma.sync bf16 3-pass GEMM; M=64 px, N=256 oc, 2 CTAs/SM -------
// smem (128B rows, XOR swizzle o^=((row&7)<<4)):
//   Ahi @0 (8192) | Alo @8192 | Bhi @16384 (32768) | Blo @49152
//   s_pk @81920 (2304) | s_wt @84224 (9216)   => total 93440
#define SMEM_MM 93440
__global__ void __launch_bounds__(256, 2) k_dconv_mma(const float* __restrict__ x, float* __restrict__ out) {
    extern __shared__ char sm[];
    uint32_t* s_pk = (uint32_t*)(sm + 81920);
    float4*   s_wt = (float4*)(sm + 84224);

    const int tid = threadIdx.x, wid = tid >> 5, lid = tid & 31;
    const int b = blockIdx.x >> 6, h = blockIdx.x & 63;
    const int m0 = (wid & 1) * 32;       // warp M origin (px within row)
    const int n0 = (wid >> 1) * 64;      // warp N origin (oc)

    // stage descriptors: 576 = 9 taps x 64 px
    for (int u = tid; u < 576; u += 256) {
        int g = blockIdx.x * 576 + u;
        s_pk[u] = g_dpk[g];
        s_wt[u] = g_dw[g];
    }

    const uint32_t smb = smem_u32(sm);
    const int ra = m0 + (lid & 15);
    const uint32_t aBase = smb + (uint32_t)ra * 128;
    const uint32_t xa = (uint32_t)(ra & 7) << 4;
    const uint32_t ca = (uint32_t)(lid >> 4) * 16;
    const int rbn = n0 + (lid & 7) + ((lid >> 4) << 3);
    const uint32_t bBase = smb + 16384 + (uint32_t)rbn * 128;
    const uint32_t xb = (uint32_t)(rbn & 7) << 4;
    const uint32_t cb = (uint32_t)((lid >> 3) & 1) * 16;

    float acc[2][8][4];
#pragma unroll
    for (int i = 0; i < 2; i++)
#pragma unroll
        for (int j = 0; j < 8; j++) {
            acc[i][j][0] = 0.f; acc[i][j][1] = 0.f; acc[i][j][2] = 0.f; acc[i][j][3] = 0.f;
        }

    const int px = tid & 63, q = tid >> 6;   // q in [0,4): k-quarter
    const float* xb0 = x + (size_t)b * C * 4096;
    __syncthreads();

    for (int chunk = 0; chunk < NCH; chunk++) {
        // B tiles: [oc][k] 128B rows, swizzled
        {
            const uint4* bh4 = g_wpack + chunk * 2048;
            const uint4* bl4 = g_wpack + (NCH + chunk) * 2048;
#pragma unroll
            for (int j = 0; j < 8; j++) {
                int u = tid + j * 256;
                uint32_t o = (uint32_t)((u >> 3) * 128 + (u & 7) * 16);
                o ^= ((uint32_t)(u >> 3) & 7) << 4;
                *(uint4*)(sm + 16384 + o) = bh4[u];
                *(uint4*)(sm + 49152 + o) = bl4[u];
            }
        }
        // A tile: sample + hi/lo split; A[px][rr], 128B rows, swizzled
        {
            char* Ah = sm; char* Al = sm + 8192;
            const uint32_t xpx = ((uint32_t)(px & 7)) << 4;
            int bm = chunk % 9;
#pragma unroll
            for (int kk = 0; kk < 9; kk++) {
                int a = kk - bm; if (a < 0) a += 9;
                int rr = a + 9 * q;                  // <= 35
                int d = kk * 64 + px;
                uint32_t pk = s_pk[d];
                float4 dw = s_wt[d];
                int i0 = pk & 0xFFF, i1 = (pk >> 12) & 0xFFF, dd = pk >> 24;
                int cl = (chunk * 64 + rr) / 9;      // stride 36 in rr => +4 channels
                const float* xp = xb0 + (size_t)cl * 4096;
                for (; rr < 64; rr += 36, xp += 4 * 4096) {
                    float v = dw.x * __ldg(xp + i0) + dw.y * __ldg(xp + i0 + dd)
                            + dw.z * __ldg(xp + i1) + dw.w * __ldg(xp + i1 + dd);
                    __nv_bfloat16 hi = __float2bfloat16(v);
                    __nv_bfloat16 lo = __float2bfloat16(v - __bfloat162float(hi));
                    uint32_t o = ((uint32_t)(px * 128 + rr * 2)) ^ xpx;
                    *(__nv_bfloat16*)(Ah + o) = hi;
                    *(__nv_bfloat16*)(Al + o) = lo;
                }
            }
        }
        __syncthreads();

#pragma unroll
        for (int ks = 0; ks < 4; ks++) {
            uint32_t aH[2][4], aL[2][4];
#pragma unroll
            for (int mm = 0; mm < 2; mm++) {
                uint32_t ad = aBase + (uint32_t)mm * 2048 + (((uint32_t)ks * 32 + ca) ^ xa);
                LDM4(aH[mm], ad);
                LDM4(aL[mm], ad + 8192);
            }
#pragma unroll
            for (int nn2 = 0; nn2 < 4; nn2++) {
                uint32_t bh[4], bl[4];
                uint32_t bd = bBase + (uint32_t)nn2 * 2048 + (((uint32_t)ks * 32 + cb) ^ xb);
                LDM4(bh, bd);
                LDM4(bl, bd + 32768);
#pragma unroll
                for (int mm = 0; mm < 2; mm++) {
                    MMA(acc[mm][2 * nn2],     aH[mm], bh[0], bh[1]);
                    MMA(acc[mm][2 * nn2 + 1], aH[mm], bh[2], bh[3]);
                    MMA(acc[mm][2 * nn2],     aL[mm], bh[0], bh[1]);
                    MMA(acc[mm][2 * nn2 + 1], aL[mm], bh[2], bh[3]);
                    MMA(acc[mm][2 * nn2],     aH[mm], bl[0], bl[1]);
                    MMA(acc[mm][2 * nn2 + 1], aH[mm], bl[2], bl[3]);
                }
            }
        }
        __syncthreads();
    }

    // epilogue: one h row; fragment mapping as verified
    {
        const int g = lid >> 2, tc = lid & 3;
#pragma unroll
        for (int mm = 0; mm < 2; mm++) {
            int px0 = m0 + mm * 16 + g, px1 = px0 + 8;
#pragma unroll
            for (int nn = 0; nn < 8; nn++) {
                int oc = n0 + nn * 8 + 2 * tc;
                size_t base = (size_t)(b * 256 + oc) * 4096 + h * 64;
                out[base + px0]        = acc[mm][nn][0];
                out[base + 4096 + px0] = acc[mm][nn][1];
                out[base + px1]        = acc[mm][nn][2];
                out[base + 4096 + px1] = acc[mm][nn][3];
            }
        }
    }
}

// ---------------------------------------------------------------------------
extern "C" void kernel_launch(void* const* d_in, const int* in_sizes, int n_in,
                              void* d_out, int out_size) {
    const float* x  = (const float*)d_in[0];
    const float* ow = (const float*)d_in[1];
    const float* ob = (const float*)d_in[2];
    const float* mw = (const float*)d_in[3];
    const float* mb = (const float*)d_in[4];
    const float* rw = (const float*)d_in[5];
    float* out = (float*)d_out;
    (void)in_sizes; (void)n_in; (void)out_size;

    cudaFuncSetAttribute(k_dconv_mma, cudaFuncAttributeMaxDynamicSharedMemorySize, SMEM_MM);
    k_prep<<<(2 * NCH * 2048 + 255) / 256, 256>>>(rw);
    k_conv_om<<<B * H, 256>>>(x, ow, ob, mw, mb);
    k_build_desc<<<(B * H * 9 * W + 255) / 256, 256>>>();
    k_dconv_mma<<<B * H, 256, SMEM_MM>>>(x, out);
}